// round 1
// baseline (speedup 1.0000x reference)
#include <cuda_runtime.h>
#include <cstdint>

#define H 128

// Scratch for segment-summed node features (G=4096 graphs max per problem spec).
__device__ float g_agg[4096 * 128];

__global__ void zero_agg_kernel(int n) {
    int i = blockIdx.x * blockDim.x + threadIdx.x;
    if (i < n) g_agg[i] = 0.0f;
}

// Segment ids are SORTED. Each block handles 128 contiguous nodes; thread t owns
// column t. Accumulate in a register while the id is constant; flush with
// atomicAdd at id boundaries (graphs can span block boundaries).
__global__ void seg_sum_kernel(const float* __restrict__ node,
                               const int* __restrict__ seg) {
    __shared__ int sseg[128];
    const int base = blockIdx.x * 128;
    const int t = threadIdx.x;
    sseg[t] = seg[base + t];
    __syncthreads();

    float acc = 0.0f;
    int cur = sseg[0];
    #pragma unroll 4
    for (int i = 0; i < 128; ++i) {
        int id = sseg[i];
        if (id != cur) {
            atomicAdd(&g_agg[cur * H + t], acc);
            acc = 0.0f;
            cur = id;
        }
        acc += node[(size_t)(base + i) * H + t];
    }
    atomicAdd(&g_agg[cur * H + t], acc);
}

// Set MLP: s = relu(relu([agg, uset] @ Ws1 + bs1) @ Ws2 + bs2)
// 8 rows per block, 128 threads (thread j = output column j).
__global__ void set_mlp_kernel(const float* __restrict__ uset,
                               const float* __restrict__ Ws1,
                               const float* __restrict__ bs1,
                               const float* __restrict__ Ws2,
                               const float* __restrict__ bs2,
                               float* __restrict__ s_out) {
    __shared__ float x[8][256];
    __shared__ float h1[8][128];
    const int j = threadIdx.x;
    const int rbase = blockIdx.x * 8;

    for (int idx = j; idx < 8 * 256; idx += 128) {
        int r = idx >> 8, k = idx & 255;
        x[r][k] = (k < 128) ? g_agg[(rbase + r) * H + k]
                            : uset[(size_t)(rbase + r) * H + (k - 128)];
    }
    __syncthreads();

    float acc[8];
    float b1 = bs1[j];
    #pragma unroll
    for (int r = 0; r < 8; ++r) acc[r] = b1;

    for (int k = 0; k < 256; ++k) {
        float w = Ws1[k * H + j];
        #pragma unroll
        for (int r = 0; r < 8; ++r) acc[r] += x[r][k] * w;
    }
    #pragma unroll
    for (int r = 0; r < 8; ++r) h1[r][j] = fmaxf(acc[r], 0.0f);
    __syncthreads();

    float b2 = bs2[j];
    #pragma unroll
    for (int r = 0; r < 8; ++r) acc[r] = b2;
    for (int k = 0; k < 128; ++k) {
        float w = Ws2[k * H + j];
        #pragma unroll
        for (int r = 0; r < 8; ++r) acc[r] += h1[r][k] * w;
    }
    #pragma unroll
    for (int r = 0; r < 8; ++r)
        s_out[(size_t)(rbase + r) * H + j] = fmaxf(acc[r], 0.0f);
}

// Node MLP: n = relu(relu([node, s[seg]] @ Wn1 + bn1) @ Wn2 + bn2)
// Block tile: 64 rows x 128 cols. 256 threads = 16x16 grid, each thread owns a
// 4-row x 8-col micro-tile (32 accumulators). Two fused GEMM stages; h1 lives
// in shared memory between stages.
#define XS_LD 68     // padded so rows 4 apart hit different banks
#define H1_LD 132    // same idea; 132*4B row stride keeps float4 alignment

__global__ void __launch_bounds__(256, 2)
node_mlp_kernel(const float* __restrict__ node,
                const int* __restrict__ seg,
                const float* __restrict__ s_in,
                const float* __restrict__ Wn1,
                const float* __restrict__ bn1,
                const float* __restrict__ Wn2,
                const float* __restrict__ bn2,
                float* __restrict__ n_out) {
    extern __shared__ float sm[];
    float (*xs)[XS_LD]  = (float (*)[XS_LD])sm;                       // [64][68]
    float (*ws)[128]    = (float (*)[128])(sm + 64 * XS_LD);          // [64][128]
    float (*h1s)[H1_LD] = (float (*)[H1_LD])(sm + 64 * XS_LD + 64 * 128); // [64][132]
    int* segs = (int*)(sm + 64 * XS_LD + 64 * 128 + 64 * H1_LD);      // [64]

    const int tid = threadIdx.x;
    const int tx = tid & 15;       // col group: cols [tx*8, tx*8+8)
    const int ty = tid >> 4;       // row group: rows [ty*4, ty*4+4)
    const int base = blockIdx.x * 64;
    const int ty4 = ty * 4;
    const int cx = tx * 8;

    if (tid < 64) segs[tid] = seg[base + tid];

    float acc[4][8];
    #pragma unroll
    for (int r = 0; r < 4; ++r)
        #pragma unroll
        for (int c = 0; c < 8; ++c) acc[r][c] = 0.0f;

    // ---- Stage A: h1 = relu([node | s_gather] @ Wn1 + bn1), K = 256 in 4 tiles
    for (int kt = 0; kt < 4; ++kt) {
        __syncthreads();
        if (kt < 2) {
            const float* src = node + (size_t)base * H + kt * 64;
            for (int idx = tid; idx < 64 * 64; idx += 256) {
                int row = idx >> 6, k = idx & 63;
                xs[row][k] = src[(size_t)row * H + k];
            }
        } else {
            const int c0 = (kt - 2) * 64;
            for (int idx = tid; idx < 64 * 64; idx += 256) {
                int row = idx >> 6, k = idx & 63;
                xs[row][k] = s_in[(size_t)segs[row] * H + c0 + k];
            }
        }
        for (int idx = tid; idx < 64 * 128; idx += 256) {
            int k = idx >> 7, j = idx & 127;
            ws[k][j] = Wn1[(size_t)(kt * 64 + k) * H + j];
        }
        __syncthreads();

        #pragma unroll 4
        for (int k = 0; k < 64; ++k) {
            float a0 = xs[ty4 + 0][k];
            float a1 = xs[ty4 + 1][k];
            float a2 = xs[ty4 + 2][k];
            float a3 = xs[ty4 + 3][k];
            float4 b0 = *(const float4*)&ws[k][cx];
            float4 b1 = *(const float4*)&ws[k][cx + 4];
            acc[0][0] += a0 * b0.x; acc[0][1] += a0 * b0.y; acc[0][2] += a0 * b0.z; acc[0][3] += a0 * b0.w;
            acc[0][4] += a0 * b1.x; acc[0][5] += a0 * b1.y; acc[0][6] += a0 * b1.z; acc[0][7] += a0 * b1.w;
            acc[1][0] += a1 * b0.x; acc[1][1] += a1 * b0.y; acc[1][2] += a1 * b0.z; acc[1][3] += a1 * b0.w;
            acc[1][4] += a1 * b1.x; acc[1][5] += a1 * b1.y; acc[1][6] += a1 * b1.z; acc[1][7] += a1 * b1.w;
            acc[2][0] += a2 * b0.x; acc[2][1] += a2 * b0.y; acc[2][2] += a2 * b0.z; acc[2][3] += a2 * b0.w;
            acc[2][4] += a2 * b1.x; acc[2][5] += a2 * b1.y; acc[2][6] += a2 * b1.z; acc[2][7] += a2 * b1.w;
            acc[3][0] += a3 * b0.x; acc[3][1] += a3 * b0.y; acc[3][2] += a3 * b0.z; acc[3][3] += a3 * b0.w;
            acc[3][4] += a3 * b1.x; acc[3][5] += a3 * b1.y; acc[3][6] += a3 * b1.z; acc[3][7] += a3 * b1.w;
        }
    }

    // bias + relu, stash h1 into shared
    {
        float4 bb0 = *(const float4*)&bn1[cx];
        float4 bb1 = *(const float4*)&bn1[cx + 4];
        #pragma unroll
        for (int r = 0; r < 4; ++r) {
            float4 v0, v1;
            v0.x = fmaxf(acc[r][0] + bb0.x, 0.0f);
            v0.y = fmaxf(acc[r][1] + bb0.y, 0.0f);
            v0.z = fmaxf(acc[r][2] + bb0.z, 0.0f);
            v0.w = fmaxf(acc[r][3] + bb0.w, 0.0f);
            v1.x = fmaxf(acc[r][4] + bb1.x, 0.0f);
            v1.y = fmaxf(acc[r][5] + bb1.y, 0.0f);
            v1.z = fmaxf(acc[r][6] + bb1.z, 0.0f);
            v1.w = fmaxf(acc[r][7] + bb1.w, 0.0f);
            *(float4*)&h1s[ty4 + r][cx] = v0;
            *(float4*)&h1s[ty4 + r][cx + 4] = v1;
        }
    }

    // ---- Stage B: out = relu(h1 @ Wn2 + bn2), K = 128 in 2 tiles
    #pragma unroll
    for (int r = 0; r < 4; ++r)
        #pragma unroll
        for (int c = 0; c < 8; ++c) acc[r][c] = 0.0f;

    for (int kt = 0; kt < 2; ++kt) {
        __syncthreads();   // h1s visible; previous compute done before ws overwrite
        for (int idx = tid; idx < 64 * 128; idx += 256) {
            int k = idx >> 7, j = idx & 127;
            ws[k][j] = Wn2[(size_t)(kt * 64 + k) * H + j];
        }
        __syncthreads();

        const int k0 = kt * 64;
        #pragma unroll 4
        for (int k = 0; k < 64; ++k) {
            float a0 = h1s[ty4 + 0][k0 + k];
            float a1 = h1s[ty4 + 1][k0 + k];
            float a2 = h1s[ty4 + 2][k0 + k];
            float a3 = h1s[ty4 + 3][k0 + k];
            float4 b0 = *(const float4*)&ws[k][cx];
            float4 b1 = *(const float4*)&ws[k][cx + 4];
            acc[0][0] += a0 * b0.x; acc[0][1] += a0 * b0.y; acc[0][2] += a0 * b0.z; acc[0][3] += a0 * b0.w;
            acc[0][4] += a0 * b1.x; acc[0][5] += a0 * b1.y; acc[0][6] += a0 * b1.z; acc[0][7] += a0 * b1.w;
            acc[1][0] += a1 * b0.x; acc[1][1] += a1 * b0.y; acc[1][2] += a1 * b0.z; acc[1][3] += a1 * b0.w;
            acc[1][4] += a1 * b1.x; acc[1][5] += a1 * b1.y; acc[1][6] += a1 * b1.z; acc[1][7] += a1 * b1.w;
            acc[2][0] += a2 * b0.x; acc[2][1] += a2 * b0.y; acc[2][2] += a2 * b0.z; acc[2][3] += a2 * b0.w;
            acc[2][4] += a2 * b1.x; acc[2][5] += a2 * b1.y; acc[2][6] += a2 * b1.z; acc[2][7] += a2 * b1.w;
            acc[3][0] += a3 * b0.x; acc[3][1] += a3 * b0.y; acc[3][2] += a3 * b0.z; acc[3][3] += a3 * b0.w;
            acc[3][4] += a3 * b1.x; acc[3][5] += a3 * b1.y; acc[3][6] += a3 * b1.z; acc[3][7] += a3 * b1.w;
        }
    }

    {
        float4 bb0 = *(const float4*)&bn2[cx];
        float4 bb1 = *(const float4*)&bn2[cx + 4];
        #pragma unroll
        for (int r = 0; r < 4; ++r) {
            float4 v0, v1;
            v0.x = fmaxf(acc[r][0] + bb0.x, 0.0f);
            v0.y = fmaxf(acc[r][1] + bb0.y, 0.0f);
            v0.z = fmaxf(acc[r][2] + bb0.z, 0.0f);
            v0.w = fmaxf(acc[r][3] + bb0.w, 0.0f);
            v1.x = fmaxf(acc[r][4] + bb1.x, 0.0f);
            v1.y = fmaxf(acc[r][5] + bb1.y, 0.0f);
            v1.z = fmaxf(acc[r][6] + bb1.z, 0.0f);
            v1.w = fmaxf(acc[r][7] + bb1.w, 0.0f);
            float* dst = n_out + (size_t)(base + ty4 + r) * H + cx;
            *(float4*)dst = v0;
            *(float4*)(dst + 4) = v1;
        }
    }
}

extern "C" void kernel_launch(void* const* d_in, const int* in_sizes, int n_in,
                              void* d_out, int out_size) {
    const float* uset  = (const float*)d_in[0];   // [G, H]
    const float* unode = (const float*)d_in[1];   // [N, H]
    const int*   seg   = (const int*)d_in[2];     // [N]
    const float* Ws1   = (const float*)d_in[3];
    const float* bs1   = (const float*)d_in[4];
    const float* Ws2   = (const float*)d_in[5];
    const float* bs2   = (const float*)d_in[6];
    const float* Wn1   = (const float*)d_in[7];
    const float* bn1   = (const float*)d_in[8];
    const float* Wn2   = (const float*)d_in[9];
    const float* bn2   = (const float*)d_in[10];

    const int G = in_sizes[0] / H;
    const int N = in_sizes[1] / H;

    float* s_out = (float*)d_out;                  // [G, H]
    float* n_out = (float*)d_out + (size_t)G * H;  // [N, H]

    zero_agg_kernel<<<(G * H + 255) / 256, 256>>>(G * H);
    seg_sum_kernel<<<N / 128, 128>>>(unode, seg);
    set_mlp_kernel<<<G / 8, 128>>>(uset, Ws1, bs1, Ws2, bs2, s_out);

    const int smem_bytes = (64 * XS_LD + 64 * 128 + 64 * H1_LD + 64) * 4;
    cudaFuncSetAttribute(node_mlp_kernel,
                         cudaFuncAttributeMaxDynamicSharedMemorySize, smem_bytes);
    node_mlp_kernel<<<N / 64, 256, smem_bytes>>>(unode, seg, s_out,
                                                 Wn1, bn1, Wn2, bn2, n_out);
}

// round 3
// speedup vs baseline: 3.4308x; 3.4308x over previous
#include <cuda_runtime.h>
#include <cstdint>

#define H 128
#define NMAX 524288

// Scratch: segment sums [G,H] and inter-layer activations h1 [N,H].
__device__ float g_agg[4096 * 128];
__device__ float g_h1[(size_t)NMAX * 128];

// ============================================================================
// Helpers (base-target PTX only: mma.sync tf32 + cvt.rna — sm_80+, no 'a' features)
// ============================================================================
__device__ __forceinline__ uint32_t f2tf32(float f) {
    uint32_t u;
    asm("cvt.rna.tf32.f32 %0, %1;" : "=r"(u) : "f"(f));
    return u;
}

__device__ __forceinline__ void mma8(float* d, const uint32_t* a,
                                     uint32_t b0, uint32_t b1) {
    asm volatile(
        "mma.sync.aligned.m16n8k8.row.col.f32.tf32.tf32.f32 "
        "{%0,%1,%2,%3},{%4,%5,%6,%7},{%8,%9},{%0,%1,%2,%3};"
        : "+f"(d[0]), "+f"(d[1]), "+f"(d[2]), "+f"(d[3])
        : "r"(a[0]), "r"(a[1]), "r"(a[2]), "r"(a[3]), "r"(b0), "r"(b1));
}

// ============================================================================
// Small kernels
// ============================================================================
__global__ void zero_agg_kernel(int n) {
    int i = blockIdx.x * blockDim.x + threadIdx.x;
    if (i < n) g_agg[i] = 0.0f;
}

__global__ void seg_sum_kernel(const float* __restrict__ node,
                               const int* __restrict__ seg) {
    __shared__ int sseg[128];
    const int base = blockIdx.x * 128;
    const int t = threadIdx.x;
    sseg[t] = seg[base + t];
    __syncthreads();
    float acc = 0.0f;
    int cur = sseg[0];
    #pragma unroll 4
    for (int i = 0; i < 128; ++i) {
        int id = sseg[i];
        if (id != cur) {
            atomicAdd(&g_agg[cur * H + t], acc);
            acc = 0.0f;
            cur = id;
        }
        acc += node[(size_t)(base + i) * H + t];
    }
    atomicAdd(&g_agg[cur * H + t], acc);
}

__global__ void set_mlp_kernel(const float* __restrict__ uset,
                               const float* __restrict__ Ws1,
                               const float* __restrict__ bs1,
                               const float* __restrict__ Ws2,
                               const float* __restrict__ bs2,
                               float* __restrict__ s_out) {
    __shared__ float x[8][256];
    __shared__ float h1[8][128];
    const int j = threadIdx.x;
    const int rbase = blockIdx.x * 8;
    for (int idx = j; idx < 8 * 256; idx += 128) {
        int r = idx >> 8, k = idx & 255;
        x[r][k] = (k < 128) ? g_agg[(rbase + r) * H + k]
                            : uset[(size_t)(rbase + r) * H + (k - 128)];
    }
    __syncthreads();
    float acc[8];
    float b1 = bs1[j];
    #pragma unroll
    for (int r = 0; r < 8; ++r) acc[r] = b1;
    for (int k = 0; k < 256; ++k) {
        float w = Ws1[k * H + j];
        #pragma unroll
        for (int r = 0; r < 8; ++r) acc[r] += x[r][k] * w;
    }
    #pragma unroll
    for (int r = 0; r < 8; ++r) h1[r][j] = fmaxf(acc[r], 0.0f);
    __syncthreads();
    float b2 = bs2[j];
    #pragma unroll
    for (int r = 0; r < 8; ++r) acc[r] = b2;
    for (int k = 0; k < 128; ++k) {
        float w = Ws2[k * H + j];
        #pragma unroll
        for (int r = 0; r < 8; ++r) acc[r] += h1[r][k] * w;
    }
    #pragma unroll
    for (int r = 0; r < 8; ++r)
        s_out[(size_t)(rbase + r) * H + j] = fmaxf(acc[r], 0.0f);
}

// ============================================================================
// Persistent mma.sync tf32 GEMM kernels.
// Block = 256 threads = 8 warps. Warp tile 32 rows x 64 cols:
//   wr = wid&3 (row slab), wc = wid>>2 (col half); [2 m-tiles][8 n-tiles] m16n8k8.
// Weights resident in SMEM as tf32 [n][k], pitch chosen so fragment LDS is
// bank-conflict-free: bank = (4*n + k) mod 32 is bijective over (8 rows, 4 cols).
// X streamed in K=64 chunks through a register prefetch + SMEM double buffer;
// conversion to tf32 (RNA) happens on the SMEM store.
// ============================================================================
#define A_LD   68      // X chunk pitch (words): 4*row+k bijective mod 32
#define W1_LD  260
#define W2_LD  132

// kernel A smem map (bytes)
#define A_W1_OFF   0                     // 128*260*4 = 133120
#define A_X0_OFF   133120                // 128*68*4 = 34816
#define A_X1_OFF   167936
#define A_B_OFF    202752                // 128 floats
#define A_SEG_OFF  203264                // 128 ints
#define A_SMEM     203776

// kernel B smem map
#define B_W2_OFF   0                     // 128*132*4 = 67584
#define B_X0_OFF   67584
#define B_X1_OFF   102400
#define B_B_OFF    137216
#define B_SMEM     137728

__global__ void __launch_bounds__(256, 1)
gemm1_kernel(const float* __restrict__ node,
             const int* __restrict__ seg,
             const float* __restrict__ s_in,
             const float* __restrict__ W1g,
             const float* __restrict__ b1g,
             int numTiles) {
    extern __shared__ __align__(16) char smem[];
    uint32_t* w1 = (uint32_t*)(smem + A_W1_OFF);
    uint32_t* xbuf[2] = {(uint32_t*)(smem + A_X0_OFF), (uint32_t*)(smem + A_X1_OFF)};
    float* bias = (float*)(smem + A_B_OFF);
    int* segs = (int*)(smem + A_SEG_OFF);

    const int tid = threadIdx.x, lane = tid & 31, wid = tid >> 5;
    const int wr = wid & 3, wc = wid >> 2, gr = lane >> 2, tg = lane & 3;
    const int ldrow = tid >> 4, ldq = tid & 15;   // staging: 16 threads per row

    // one-time: W1 (global [k=256][n=128]) -> smem [n][k] tf32
    for (int idx = tid; idx < 128 * 256; idx += 256) {
        int n = idx >> 8, k = idx & 255;
        w1[n * W1_LD + k] = f2tf32(W1g[k * H + n]);
    }
    if (tid < 128) bias[tid] = b1g[tid];
    __syncthreads();

    float acc[2][8][4];
    #pragma unroll
    for (int mt = 0; mt < 2; ++mt)
        #pragma unroll
        for (int nt = 0; nt < 8; ++nt)
            #pragma unroll
            for (int j = 0; j < 4; ++j) acc[mt][nt][j] = 0.0f;

    for (int tile = blockIdx.x; tile < numTiles; tile += gridDim.x) {
        const int base = tile * 128;
        if (tid < 128) segs[tid] = seg[base + tid];

        // prefetch chunk 0 (node, cols 0..63) into regs
        float4 pre[8];
        #pragma unroll
        for (int it = 0; it < 8; ++it) {
            int row = ldrow + it * 16;
            pre[it] = *(const float4*)&node[(size_t)(base + row) * H + ldq * 4];
        }

        for (int c = 0; c < 4; ++c) {
            // store+convert chunk c into smem buffer
            uint32_t* xs = xbuf[c & 1];
            #pragma unroll
            for (int it = 0; it < 8; ++it) {
                int row = ldrow + it * 16;
                uint4 v;
                v.x = f2tf32(pre[it].x); v.y = f2tf32(pre[it].y);
                v.z = f2tf32(pre[it].z); v.w = f2tf32(pre[it].w);
                *(uint4*)(xs + row * A_LD + ldq * 4) = v;
            }
            // prefetch chunk c+1
            if (c < 3) {
                const int cn = c + 1;
                #pragma unroll
                for (int it = 0; it < 8; ++it) {
                    int row = ldrow + it * 16;
                    const float* src = (cn < 2)
                        ? &node[(size_t)(base + row) * H + cn * 64 + ldq * 4]
                        : &s_in[(size_t)segs[row] * H + (cn - 2) * 64 + ldq * 4];
                    pre[it] = *(const float4*)src;
                }
            }
            __syncthreads();   // stores visible

            // mma over this chunk (8 k8-steps)
            const int kkb = c * 64;
            #pragma unroll
            for (int ks = 0; ks < 8; ++ks) {
                uint32_t a[2][4];
                #pragma unroll
                for (int mt = 0; mt < 2; ++mt) {
                    const int r0 = wr * 32 + mt * 16 + gr;
                    a[mt][0] = xs[r0 * A_LD + ks * 8 + tg];
                    a[mt][1] = xs[(r0 + 8) * A_LD + ks * 8 + tg];
                    a[mt][2] = xs[r0 * A_LD + ks * 8 + tg + 4];
                    a[mt][3] = xs[(r0 + 8) * A_LD + ks * 8 + tg + 4];
                }
                #pragma unroll
                for (int nt = 0; nt < 8; ++nt) {
                    const int n = wc * 64 + nt * 8 + gr;
                    uint32_t b0 = w1[n * W1_LD + kkb + ks * 8 + tg];
                    uint32_t b1 = w1[n * W1_LD + kkb + ks * 8 + tg + 4];
                    mma8(acc[0][nt], a[0], b0, b1);
                    mma8(acc[1][nt], a[1], b0, b1);
                }
            }
            __syncthreads();   // mma done before buffer reuse / segs rewrite
        }

        // epilogue: bias + relu -> g_h1
        #pragma unroll
        for (int mt = 0; mt < 2; ++mt) {
            const int r0 = base + wr * 32 + mt * 16 + gr;
            #pragma unroll
            for (int nt = 0; nt < 8; ++nt) {
                const int col = wc * 64 + nt * 8 + 2 * tg;
                const float bx = bias[col], by = bias[col + 1];
                float2 v;
                v.x = fmaxf(acc[mt][nt][0] + bx, 0.0f);
                v.y = fmaxf(acc[mt][nt][1] + by, 0.0f);
                *(float2*)&g_h1[(size_t)r0 * H + col] = v;
                v.x = fmaxf(acc[mt][nt][2] + bx, 0.0f);
                v.y = fmaxf(acc[mt][nt][3] + by, 0.0f);
                *(float2*)&g_h1[(size_t)(r0 + 8) * H + col] = v;
                #pragma unroll
                for (int j = 0; j < 4; ++j) acc[mt][nt][j] = 0.0f;
            }
        }
    }
}

__global__ void __launch_bounds__(256, 1)
gemm2_kernel(const float* __restrict__ W2g,
             const float* __restrict__ b2g,
             float* __restrict__ n_out,
             int numTiles) {
    extern __shared__ __align__(16) char smem[];
    uint32_t* w2 = (uint32_t*)(smem + B_W2_OFF);
    uint32_t* xbuf[2] = {(uint32_t*)(smem + B_X0_OFF), (uint32_t*)(smem + B_X1_OFF)};
    float* bias = (float*)(smem + B_B_OFF);

    const int tid = threadIdx.x, lane = tid & 31, wid = tid >> 5;
    const int wr = wid & 3, wc = wid >> 2, gr = lane >> 2, tg = lane & 3;
    const int ldrow = tid >> 4, ldq = tid & 15;

    for (int idx = tid; idx < 128 * 128; idx += 256) {
        int n = idx >> 7, k = idx & 127;
        w2[n * W2_LD + k] = f2tf32(W2g[k * H + n]);
    }
    if (tid < 128) bias[tid] = b2g[tid];
    __syncthreads();

    float acc[2][8][4];
    #pragma unroll
    for (int mt = 0; mt < 2; ++mt)
        #pragma unroll
        for (int nt = 0; nt < 8; ++nt)
            #pragma unroll
            for (int j = 0; j < 4; ++j) acc[mt][nt][j] = 0.0f;

    for (int tile = blockIdx.x; tile < numTiles; tile += gridDim.x) {
        const int base = tile * 128;

        float4 pre[8];
        #pragma unroll
        for (int it = 0; it < 8; ++it) {
            int row = ldrow + it * 16;
            pre[it] = *(const float4*)&g_h1[(size_t)(base + row) * H + ldq * 4];
        }

        for (int c = 0; c < 2; ++c) {
            uint32_t* xs = xbuf[c & 1];
            #pragma unroll
            for (int it = 0; it < 8; ++it) {
                int row = ldrow + it * 16;
                uint4 v;
                v.x = f2tf32(pre[it].x); v.y = f2tf32(pre[it].y);
                v.z = f2tf32(pre[it].z); v.w = f2tf32(pre[it].w);
                *(uint4*)(xs + row * A_LD + ldq * 4) = v;
            }
            if (c < 1) {
                #pragma unroll
                for (int it = 0; it < 8; ++it) {
                    int row = ldrow + it * 16;
                    pre[it] = *(const float4*)&g_h1[(size_t)(base + row) * H + 64 + ldq * 4];
                }
            }
            __syncthreads();

            const int kkb = c * 64;
            #pragma unroll
            for (int ks = 0; ks < 8; ++ks) {
                uint32_t a[2][4];
                #pragma unroll
                for (int mt = 0; mt < 2; ++mt) {
                    const int r0 = wr * 32 + mt * 16 + gr;
                    a[mt][0] = xs[r0 * A_LD + ks * 8 + tg];
                    a[mt][1] = xs[(r0 + 8) * A_LD + ks * 8 + tg];
                    a[mt][2] = xs[r0 * A_LD + ks * 8 + tg + 4];
                    a[mt][3] = xs[(r0 + 8) * A_LD + ks * 8 + tg + 4];
                }
                #pragma unroll
                for (int nt = 0; nt < 8; ++nt) {
                    const int n = wc * 64 + nt * 8 + gr;
                    uint32_t b0 = w2[n * W2_LD + kkb + ks * 8 + tg];
                    uint32_t b1 = w2[n * W2_LD + kkb + ks * 8 + tg + 4];
                    mma8(acc[0][nt], a[0], b0, b1);
                    mma8(acc[1][nt], a[1], b0, b1);
                }
            }
            __syncthreads();
        }

        #pragma unroll
        for (int mt = 0; mt < 2; ++mt) {
            const int r0 = base + wr * 32 + mt * 16 + gr;
            #pragma unroll
            for (int nt = 0; nt < 8; ++nt) {
                const int col = wc * 64 + nt * 8 + 2 * tg;
                const float bx = bias[col], by = bias[col + 1];
                float2 v;
                v.x = fmaxf(acc[mt][nt][0] + bx, 0.0f);
                v.y = fmaxf(acc[mt][nt][1] + by, 0.0f);
                *(float2*)&n_out[(size_t)r0 * H + col] = v;
                v.x = fmaxf(acc[mt][nt][2] + bx, 0.0f);
                v.y = fmaxf(acc[mt][nt][3] + by, 0.0f);
                *(float2*)&n_out[(size_t)(r0 + 8) * H + col] = v;
                #pragma unroll
                for (int j = 0; j < 4; ++j) acc[mt][nt][j] = 0.0f;
            }
        }
    }
}

extern "C" void kernel_launch(void* const* d_in, const int* in_sizes, int n_in,
                              void* d_out, int out_size) {
    const float* uset  = (const float*)d_in[0];   // [G, H]
    const float* unode = (const float*)d_in[1];   // [N, H]
    const int*   seg   = (const int*)d_in[2];     // [N]
    const float* Ws1   = (const float*)d_in[3];
    const float* bs1   = (const float*)d_in[4];
    const float* Ws2   = (const float*)d_in[5];
    const float* bs2   = (const float*)d_in[6];
    const float* Wn1   = (const float*)d_in[7];
    const float* bn1   = (const float*)d_in[8];
    const float* Wn2   = (const float*)d_in[9];
    const float* bn2   = (const float*)d_in[10];

    const int G = in_sizes[0] / H;
    const int N = in_sizes[1] / H;

    float* s_out = (float*)d_out;                  // [G, H]
    float* n_out = (float*)d_out + (size_t)G * H;  // [N, H]

    zero_agg_kernel<<<(G * H + 255) / 256, 256>>>(G * H);
    seg_sum_kernel<<<N / 128, 128>>>(unode, seg);
    set_mlp_kernel<<<G / 8, 128>>>(uset, Ws1, bs1, Ws2, bs2, s_out);

    static int smem_set = 0;
    if (!smem_set) {
        cudaFuncSetAttribute(gemm1_kernel,
                             cudaFuncAttributeMaxDynamicSharedMemorySize, A_SMEM);
        cudaFuncSetAttribute(gemm2_kernel,
                             cudaFuncAttributeMaxDynamicSharedMemorySize, B_SMEM);
        smem_set = 1;
    }
    const int numTiles = N / 128;
    const int grid = numTiles < 148 ? numTiles : 148;
    gemm1_kernel<<<grid, 256, A_SMEM>>>(unode, seg, s_out, Wn1, bn1, numTiles);
    gemm2_kernel<<<grid, 256, B_SMEM>>>(Wn2, bn2, n_out, numTiles);
}

// round 4
// speedup vs baseline: 5.1511x; 1.5014x over previous
#include <cuda_runtime.h>
#include <cstdint>

#define H 128

// Scratch: segment sums [G,H]; c[g] = s[g] @ W1[128:256] + b1  (fp32).
__device__ float g_agg[4096 * 128];
__device__ float g_c[4096 * 128];

// ============================================================================
// Base-target PTX helpers (no 'a'-suffix features)
// ============================================================================
__device__ __forceinline__ uint32_t f2tf32(float f) {
    uint32_t u;
    asm("cvt.rna.tf32.f32 %0, %1;" : "=r"(u) : "f"(f));
    return u;
}
__device__ __forceinline__ uint32_t smem_u32_of(const void* p) {
    uint32_t a;
    asm("{ .reg .u64 t; cvta.to.shared.u64 t, %1; cvt.u32.u64 %0, t; }"
        : "=r"(a) : "l"(p));
    return a;
}
__device__ __forceinline__ void mma8(float* d, const uint32_t* a,
                                     uint32_t b0, uint32_t b1) {
    asm volatile(
        "mma.sync.aligned.m16n8k8.row.col.f32.tf32.tf32.f32 "
        "{%0,%1,%2,%3},{%4,%5,%6,%7},{%8,%9},{%0,%1,%2,%3};"
        : "+f"(d[0]), "+f"(d[1]), "+f"(d[2]), "+f"(d[3])
        : "r"(a[0]), "r"(a[1]), "r"(a[2]), "r"(a[3]), "r"(b0), "r"(b1));
}
__device__ __forceinline__ void ldsm4(uint32_t& r0, uint32_t& r1,
                                      uint32_t& r2, uint32_t& r3, uint32_t addr) {
    asm volatile("ldmatrix.sync.aligned.m8n8.x4.shared.b16 {%0,%1,%2,%3}, [%4];"
                 : "=r"(r0), "=r"(r1), "=r"(r2), "=r"(r3) : "r"(addr));
}

// ============================================================================
// Small kernels
// ============================================================================
__global__ void zero_agg_kernel(int n) {
    int i = blockIdx.x * blockDim.x + threadIdx.x;
    if (i < n) g_agg[i] = 0.0f;
}

__global__ void seg_sum_kernel(const float* __restrict__ node,
                               const int* __restrict__ seg) {
    __shared__ int sseg[128];
    const int base = blockIdx.x * 128;
    const int t = threadIdx.x;
    sseg[t] = seg[base + t];
    __syncthreads();
    float acc = 0.0f;
    int cur = sseg[0];
    #pragma unroll 4
    for (int i = 0; i < 128; ++i) {
        int id = sseg[i];
        if (id != cur) {
            atomicAdd(&g_agg[cur * H + t], acc);
            acc = 0.0f;
            cur = id;
        }
        acc += node[(size_t)(base + i) * H + t];
    }
    atomicAdd(&g_agg[cur * H + t], acc);
}

__global__ void set_mlp_kernel(const float* __restrict__ uset,
                               const float* __restrict__ Ws1,
                               const float* __restrict__ bs1,
                               const float* __restrict__ Ws2,
                               const float* __restrict__ bs2,
                               float* __restrict__ s_out) {
    __shared__ float x[8][256];
    __shared__ float h1[8][128];
    const int j = threadIdx.x;
    const int rbase = blockIdx.x * 8;
    for (int idx = j; idx < 8 * 256; idx += 128) {
        int r = idx >> 8, k = idx & 255;
        x[r][k] = (k < 128) ? g_agg[(rbase + r) * H + k]
                            : uset[(size_t)(rbase + r) * H + (k - 128)];
    }
    __syncthreads();
    float acc[8];
    float b1 = bs1[j];
    #pragma unroll
    for (int r = 0; r < 8; ++r) acc[r] = b1;
    for (int k = 0; k < 256; ++k) {
        float w = Ws1[k * H + j];
        #pragma unroll
        for (int r = 0; r < 8; ++r) acc[r] += x[r][k] * w;
    }
    #pragma unroll
    for (int r = 0; r < 8; ++r) h1[r][j] = fmaxf(acc[r], 0.0f);
    __syncthreads();
    float b2 = bs2[j];
    #pragma unroll
    for (int r = 0; r < 8; ++r) acc[r] = b2;
    for (int k = 0; k < 128; ++k) {
        float w = Ws2[k * H + j];
        #pragma unroll
        for (int r = 0; r < 8; ++r) acc[r] += h1[r][k] * w;
    }
    #pragma unroll
    for (int r = 0; r < 8; ++r)
        s_out[(size_t)(rbase + r) * H + j] = fmaxf(acc[r], 0.0f);
}

// c[g][n] = b1[n] + sum_k s[g][k] * W1[(128+k)*H + n]   (exact fp32)
__global__ void c_kernel(const float* __restrict__ s_out,
                         const float* __restrict__ W1g,
                         const float* __restrict__ b1g) {
    __shared__ float xs[8][128];
    const int j = threadIdx.x;
    const int g0 = blockIdx.x * 8;
    for (int idx = j; idx < 8 * 128; idx += 128)
        xs[idx >> 7][idx & 127] = s_out[(size_t)(g0 + (idx >> 7)) * H + (idx & 127)];
    __syncthreads();
    float acc[8];
    float b = b1g[j];
    #pragma unroll
    for (int r = 0; r < 8; ++r) acc[r] = b;
    for (int k = 0; k < 128; ++k) {
        float w = W1g[(size_t)(128 + k) * H + j];
        #pragma unroll
        for (int r = 0; r < 8; ++r) acc[r] += xs[r][k] * w;
    }
    #pragma unroll
    for (int r = 0; r < 8; ++r) g_c[(size_t)(g0 + r) * H + j] = acc[r];
}

// ============================================================================
// Fused node MLP: persistent, 512 threads, ldmatrix + mma.sync tf32.
//   layer1: acc = X[128rows,128k] @ W1a ; + c[seg] ; relu -> h1 (tf32, smem)
//   layer2: out = h1 @ W2 + b2 ; relu -> global
// SMEM (bytes): W1a 65536 | W2 65536 | X/h1 65536 | b2 512 | segs 512
// Weight layout [n][128k] tf32, 512B/row, group-swizzle g=(k>>2)^(n&7).
// X chunks [128r][64k], 256B/row, g=(k>>2)^(r&7). h1 [128r][128k], 512B/row.
// ============================================================================
#define W1_OFF   0
#define W2_OFF   65536
#define X_OFF    131072
#define X1_OFF   163840
#define B2_OFF   196608
#define SEG_OFF  197120
#define F_SMEM   197632

__global__ void __launch_bounds__(512, 1)
fused_node_mlp(const float* __restrict__ node,
               const int* __restrict__ seg,
               const float* __restrict__ W1g,
               const float* __restrict__ W2g,
               const float* __restrict__ b2g,
               float* __restrict__ n_out,
               int numTiles) {
    extern __shared__ __align__(16) char smem[];
    const uint32_t sb = smem_u32_of(smem);
    float* b2s = (float*)(smem + B2_OFF);
    int* segs = (int*)(smem + SEG_OFF);

    const int tid = threadIdx.x, lane = tid & 31, wid = tid >> 5;
    const int wr = wid & 3, wc = wid >> 2;          // warp tile: rows wr*32, cols wc*32
    const int gr = lane >> 2, tg = lane & 3;
    const int ldrow = tid >> 4, ldq = tid & 15;     // X staging
    const int lxr = ldrow & 7;

    // --- one-time: weights -> smem tf32 swizzled, bias ---
    for (int idx = tid; idx < 128 * 128; idx += 512) {
        int n = idx >> 7, k = idx & 127;
        uint32_t off = (uint32_t)n * 512u + ((((uint32_t)k >> 2) ^ (n & 7)) << 4)
                     + ((uint32_t)k & 3) * 4u;
        *(uint32_t*)(smem + W1_OFF + off) = f2tf32(W1g[(size_t)k * H + n]);
        *(uint32_t*)(smem + W2_OFF + off) = f2tf32(W2g[(size_t)k * H + n]);
    }
    if (tid < 128) b2s[tid] = b2g[tid];

    // --- ldsm per-lane constants ---
    // A: matrix = lane>>3: row = wr*32 + mt*16 + (matrix&1)*8 + (lane&7); h = matrix>>1
    const int subA = lane & 7;
    const int arow0 = wr * 32 + ((lane >> 3) & 1) * 8 + subA;       // mt=0
    const int hA = lane >> 4;                                       // matrix>>1
    // B: n = wc*32 + p*16 + ((lane>>4)&1)*8 + (lane&7); h = (lane>>3)&1
    const int subB = lane & 7;
    const int brow0 = wc * 32 + ((lane >> 4) & 1) * 8 + subB;       // p=0
    const int hB = (lane >> 3) & 1;

    __syncthreads();

    float acc[2][4][4];
    float4 pre[4];

    // prefetch chunk0 of first tile
    {
        int base = blockIdx.x * 128;
        #pragma unroll
        for (int it = 0; it < 4; ++it) {
            int row = ldrow + it * 32;
            pre[it] = *(const float4*)&node[(size_t)(base + row) * H + ldq * 4];
        }
    }

    for (int tile = blockIdx.x; tile < numTiles; tile += gridDim.x) {
        const int base = tile * 128;

        // STS chunk0 (cvt to tf32, swizzled)
        #pragma unroll
        for (int it = 0; it < 4; ++it) {
            int row = ldrow + it * 32;
            uint4 v;
            v.x = f2tf32(pre[it].x); v.y = f2tf32(pre[it].y);
            v.z = f2tf32(pre[it].z); v.w = f2tf32(pre[it].w);
            *(uint4*)(smem + X_OFF + row * 256 + ((ldq ^ lxr) << 4)) = v;
        }
        if (tid < 128) segs[tid] = seg[base + tid];
        // prefetch chunk1
        #pragma unroll
        for (int it = 0; it < 4; ++it) {
            int row = ldrow + it * 32;
            pre[it] = *(const float4*)&node[(size_t)(base + row) * H + 64 + ldq * 4];
        }
        __syncthreads();

        // STS chunk1 (xbuf1 not read until after next barrier)
        #pragma unroll
        for (int it = 0; it < 4; ++it) {
            int row = ldrow + it * 32;
            uint4 v;
            v.x = f2tf32(pre[it].x); v.y = f2tf32(pre[it].y);
            v.z = f2tf32(pre[it].z); v.w = f2tf32(pre[it].w);
            *(uint4*)(smem + X1_OFF + row * 256 + ((ldq ^ lxr) << 4)) = v;
        }

        #pragma unroll
        for (int mt = 0; mt < 2; ++mt)
            #pragma unroll
            for (int nt = 0; nt < 4; ++nt)
                #pragma unroll
                for (int j = 0; j < 4; ++j) acc[mt][nt][j] = 0.0f;

        // ---- layer1 mma: 2 chunks of K=64 ----
        #pragma unroll
        for (int c = 0; c < 2; ++c) {
            const uint32_t xb = sb + (c ? X1_OFF : X_OFF);
            const int kqb = c * 16;
            #pragma unroll
            for (int ks = 0; ks < 8; ++ks) {
                uint32_t A[2][4], B[2][4];
                #pragma unroll
                for (int mt = 0; mt < 2; ++mt) {
                    uint32_t ad = xb + (uint32_t)(arow0 + mt * 16) * 256u
                                + ((((ks << 1) + hA) ^ subA) << 4);
                    ldsm4(A[mt][0], A[mt][1], A[mt][2], A[mt][3], ad);
                }
                #pragma unroll
                for (int p = 0; p < 2; ++p) {
                    uint32_t bd = sb + W1_OFF + (uint32_t)(brow0 + p * 16) * 512u
                                + (((kqb + (ks << 1) + hB) ^ subB) << 4);
                    ldsm4(B[p][0], B[p][1], B[p][2], B[p][3], bd);
                }
                #pragma unroll
                for (int mt = 0; mt < 2; ++mt) {
                    mma8(acc[mt][0], A[mt], B[0][0], B[0][1]);
                    mma8(acc[mt][1], A[mt], B[0][2], B[0][3]);
                    mma8(acc[mt][2], A[mt], B[1][0], B[1][1]);
                    mma8(acc[mt][3], A[mt], B[1][2], B[1][3]);
                }
            }
            __syncthreads();   // c=0: chunk1 STS visible / c=1: all reads done
        }

        // ---- epilogue1: + c[seg], relu, tf32 -> h1 (overwrites X region) ----
        {
            const int colb = wc * 32 + 2 * tg;
            #pragma unroll
            for (int mt = 0; mt < 2; ++mt) {
                const int ra = wr * 32 + mt * 16 + gr;
                const int ga = segs[ra], gb = segs[ra + 8];
                #pragma unroll
                for (int nt = 0; nt < 4; ++nt) {
                    const int col = colb + nt * 8;
                    float2 ca = *(const float2*)&g_c[(size_t)ga * H + col];
                    float2 cb = *(const float2*)&g_c[(size_t)gb * H + col];
                    uint32_t g = ((uint32_t)col >> 2) ^ (uint32_t)gr;
                    uint32_t bo = (g << 4) + ((uint32_t)col & 3) * 4u;
                    uint2 v;
                    v.x = f2tf32(fmaxf(acc[mt][nt][0] + ca.x, 0.0f));
                    v.y = f2tf32(fmaxf(acc[mt][nt][1] + ca.y, 0.0f));
                    *(uint2*)(smem + X_OFF + ra * 512 + bo) = v;
                    v.x = f2tf32(fmaxf(acc[mt][nt][2] + cb.x, 0.0f));
                    v.y = f2tf32(fmaxf(acc[mt][nt][3] + cb.y, 0.0f));
                    *(uint2*)(smem + X_OFF + (ra + 8) * 512 + bo) = v;
                    #pragma unroll
                    for (int j = 0; j < 4; ++j) acc[mt][nt][j] = 0.0f;
                }
            }
        }
        __syncthreads();

        // prefetch next tile chunk0 (overlaps layer2)
        if (tile + gridDim.x < numTiles) {
            const int nb = (tile + gridDim.x) * 128;
            #pragma unroll
            for (int it = 0; it < 4; ++it) {
                int row = ldrow + it * 32;
                pre[it] = *(const float4*)&node[(size_t)(nb + row) * H + ldq * 4];
            }
        }

        // ---- layer2 mma: h1 [128r][128k] (512B rows) @ W2 ----
        #pragma unroll
        for (int ks = 0; ks < 16; ++ks) {
            uint32_t A[2][4], B[2][4];
            #pragma unroll
            for (int mt = 0; mt < 2; ++mt) {
                uint32_t ad = sb + X_OFF + (uint32_t)(arow0 + mt * 16) * 512u
                            + ((((ks << 1) + hA) ^ subA) << 4);
                ldsm4(A[mt][0], A[mt][1], A[mt][2], A[mt][3], ad);
            }
            #pragma unroll
            for (int p = 0; p < 2; ++p) {
                uint32_t bd = sb + W2_OFF + (uint32_t)(brow0 + p * 16) * 512u
                            + ((((ks << 1) + hB) ^ subB) << 4);
                ldsm4(B[p][0], B[p][1], B[p][2], B[p][3], bd);
            }
            #pragma unroll
            for (int mt = 0; mt < 2; ++mt) {
                mma8(acc[mt][0], A[mt], B[0][0], B[0][1]);
                mma8(acc[mt][1], A[mt], B[0][2], B[0][3]);
                mma8(acc[mt][2], A[mt], B[1][0], B[1][1]);
                mma8(acc[mt][3], A[mt], B[1][2], B[1][3]);
            }
        }

        // ---- epilogue2: +b2, relu, STG ----
        {
            const int colb = wc * 32 + 2 * tg;
            #pragma unroll
            for (int mt = 0; mt < 2; ++mt) {
                const int ra = base + wr * 32 + mt * 16 + gr;
                #pragma unroll
                for (int nt = 0; nt < 4; ++nt) {
                    const int col = colb + nt * 8;
                    const float bx = b2s[col], by = b2s[col + 1];
                    float2 v;
                    v.x = fmaxf(acc[mt][nt][0] + bx, 0.0f);
                    v.y = fmaxf(acc[mt][nt][1] + by, 0.0f);
                    *(float2*)&n_out[(size_t)ra * H + col] = v;
                    v.x = fmaxf(acc[mt][nt][2] + bx, 0.0f);
                    v.y = fmaxf(acc[mt][nt][3] + by, 0.0f);
                    *(float2*)&n_out[(size_t)(ra + 8) * H + col] = v;
                }
            }
        }
        __syncthreads();   // protect h1/X region before next tile's STS
    }
}

extern "C" void kernel_launch(void* const* d_in, const int* in_sizes, int n_in,
                              void* d_out, int out_size) {
    const float* uset  = (const float*)d_in[0];   // [G, H]
    const float* unode = (const float*)d_in[1];   // [N, H]
    const int*   seg   = (const int*)d_in[2];     // [N]
    const float* Ws1   = (const float*)d_in[3];
    const float* bs1   = (const float*)d_in[4];
    const float* Ws2   = (const float*)d_in[5];
    const float* bs2   = (const float*)d_in[6];
    const float* Wn1   = (const float*)d_in[7];
    const float* bn1   = (const float*)d_in[8];
    const float* Wn2   = (const float*)d_in[9];
    const float* bn2   = (const float*)d_in[10];

    const int G = in_sizes[0] / H;
    const int N = in_sizes[1] / H;

    float* s_out = (float*)d_out;                  // [G, H]
    float* n_out = (float*)d_out + (size_t)G * H;  // [N, H]

    zero_agg_kernel<<<(G * H + 255) / 256, 256>>>(G * H);
    seg_sum_kernel<<<N / 128, 128>>>(unode, seg);
    set_mlp_kernel<<<G / 8, 128>>>(uset, Ws1, bs1, Ws2, bs2, s_out);
    c_kernel<<<G / 8, 128>>>(s_out, Wn1, bn1);

    static int smem_set = 0;
    if (!smem_set) {
        cudaFuncSetAttribute(fused_node_mlp,
                             cudaFuncAttributeMaxDynamicSharedMemorySize, F_SMEM);
        smem_set = 1;
    }
    const int numTiles = N / 128;
    const int grid = numTiles < 148 ? numTiles : 148;
    fused_node_mlp<<<grid, 512, F_SMEM>>>(unode, seg, Wn1, Wn2, bn2, n_out, numTiles);
}

// round 6
// speedup vs baseline: 5.2877x; 1.0265x over previous
#include <cuda_runtime.h>
#include <cstdint>

#define H 128

// Scratch: segment sums [G,H]; c[g] = s[g] @ W1[128:256] + b1  (fp32).
__device__ float g_agg[4096 * 128];
__device__ float g_c[4096 * 128];

// ============================================================================
// Base-target PTX helpers (no 'a'-suffix features)
// ============================================================================
__device__ __forceinline__ uint32_t f2tf32(float f) {
    uint32_t u;
    asm("cvt.rna.tf32.f32 %0, %1;" : "=r"(u) : "f"(f));
    return u;
}
__device__ __forceinline__ uint32_t smem_u32_of(const void* p) {
    uint32_t a;
    asm("{ .reg .u64 t; cvta.to.shared.u64 t, %1; cvt.u32.u64 %0, t; }"
        : "=r"(a) : "l"(p));
    return a;
}
__device__ __forceinline__ void mma8(float* d, const uint32_t* a,
                                     uint32_t b0, uint32_t b1) {
    asm volatile(
        "mma.sync.aligned.m16n8k8.row.col.f32.tf32.tf32.f32 "
        "{%0,%1,%2,%3},{%4,%5,%6,%7},{%8,%9},{%0,%1,%2,%3};"
        : "+f"(d[0]), "+f"(d[1]), "+f"(d[2]), "+f"(d[3])
        : "r"(a[0]), "r"(a[1]), "r"(a[2]), "r"(a[3]), "r"(b0), "r"(b1));
}
__device__ __forceinline__ void ldsm4(uint32_t& r0, uint32_t& r1,
                                      uint32_t& r2, uint32_t& r3, uint32_t addr) {
    asm volatile("ldmatrix.sync.aligned.m8n8.x4.shared.b16 {%0,%1,%2,%3}, [%4];"
                 : "=r"(r0), "=r"(r1), "=r"(r2), "=r"(r3) : "r"(addr));
}
#define CP_ASYNC16(dst, src) \
    asm volatile("cp.async.cg.shared.global [%0], [%1], 16;" :: "r"(dst), "l"(src))
#define CP_COMMIT() asm volatile("cp.async.commit_group;" ::: "memory")
#define CP_WAIT(n)  asm volatile("cp.async.wait_group %0;" :: "n"(n) : "memory")

// ============================================================================
// Small kernels
// ============================================================================
__global__ void zero_agg_kernel(int n) {
    int i = blockIdx.x * blockDim.x + threadIdx.x;
    if (i < n) g_agg[i] = 0.0f;
}

__global__ void seg_sum_kernel(const float* __restrict__ node,
                               const int* __restrict__ seg) {
    __shared__ int sseg[128];
    const int base = blockIdx.x * 128;
    const int t = threadIdx.x;
    sseg[t] = seg[base + t];
    __syncthreads();
    float acc = 0.0f;
    int cur = sseg[0];
    #pragma unroll 4
    for (int i = 0; i < 128; ++i) {
        int id = sseg[i];
        if (id != cur) {
            atomicAdd(&g_agg[cur * H + t], acc);
            acc = 0.0f;
            cur = id;
        }
        acc += node[(size_t)(base + i) * H + t];
    }
    atomicAdd(&g_agg[cur * H + t], acc);
}

// set MLP + per-graph constant c[g] = s[g] @ W1[128:256] + b1 (exact fp32)
__global__ void set_mlp_c_kernel(const float* __restrict__ uset,
                                 const float* __restrict__ Ws1,
                                 const float* __restrict__ bs1,
                                 const float* __restrict__ Ws2,
                                 const float* __restrict__ bs2,
                                 const float* __restrict__ W1g,
                                 const float* __restrict__ b1g,
                                 float* __restrict__ s_out) {
    __shared__ float x[8][256];
    __shared__ float h1[8][128];
    __shared__ float sres[8][128];
    const int j = threadIdx.x;
    const int rbase = blockIdx.x * 8;
    for (int idx = j; idx < 8 * 256; idx += 128) {
        int r = idx >> 8, k = idx & 255;
        x[r][k] = (k < 128) ? g_agg[(rbase + r) * H + k]
                            : uset[(size_t)(rbase + r) * H + (k - 128)];
    }
    __syncthreads();
    float acc[8];
    float b1 = bs1[j];
    #pragma unroll
    for (int r = 0; r < 8; ++r) acc[r] = b1;
    for (int k = 0; k < 256; ++k) {
        float w = Ws1[k * H + j];
        #pragma unroll
        for (int r = 0; r < 8; ++r) acc[r] += x[r][k] * w;
    }
    #pragma unroll
    for (int r = 0; r < 8; ++r) h1[r][j] = fmaxf(acc[r], 0.0f);
    __syncthreads();
    float b2 = bs2[j];
    #pragma unroll
    for (int r = 0; r < 8; ++r) acc[r] = b2;
    for (int k = 0; k < 128; ++k) {
        float w = Ws2[k * H + j];
        #pragma unroll
        for (int r = 0; r < 8; ++r) acc[r] += h1[r][k] * w;
    }
    #pragma unroll
    for (int r = 0; r < 8; ++r) {
        float v = fmaxf(acc[r], 0.0f);
        sres[r][j] = v;
        s_out[(size_t)(rbase + r) * H + j] = v;
    }
    __syncthreads();
    // c = sres @ W1b + b1g
    float bb = b1g[j];
    #pragma unroll
    for (int r = 0; r < 8; ++r) acc[r] = bb;
    for (int k = 0; k < 128; ++k) {
        float w = W1g[(size_t)(128 + k) * H + j];
        #pragma unroll
        for (int r = 0; r < 8; ++r) acc[r] += sres[r][k] * w;
    }
    #pragma unroll
    for (int r = 0; r < 8; ++r) g_c[(size_t)(rbase + r) * H + j] = acc[r];
}

// ============================================================================
// Fused node MLP, persistent, 512 threads, cp.async 3-buffer rotation.
//   layer1: acc = X[128r,128k] @ W1a ; + c[seg] ; relu -> h (tf32, 2 half-bufs)
//   layer2: out = h @ W2 + b2 ; relu -> global
// Buffers: 3 x 32KB chunks [128r][64k], 256B/row, swizzle g=(k>>2)^(r&7).
// Weights [n][128k] tf32, 512B/row, swizzle g=(k>>2)^(n&7).
// X fed raw fp32 (tf32 truncation); h converted RNA.
// ============================================================================
#define W1_OFF   0
#define W2_OFF   65536
#define BUF0     131072
#define BUF1     163840
#define BUF2     196608
#define B2S_OFF  229376
#define SEG_OFF  229888
#define F_SMEM   230400

__global__ void __launch_bounds__(512, 1)
fused_node_mlp(const float* __restrict__ node,
               const int* __restrict__ seg,
               const float* __restrict__ W1g,
               const float* __restrict__ W2g,
               const float* __restrict__ b2g,
               float* __restrict__ n_out,
               int numTiles) {
    extern __shared__ __align__(16) char smem[];
    const uint32_t sb = smem_u32_of(smem);
    float* b2s = (float*)(smem + B2S_OFF);
    int* segs = (int*)(smem + SEG_OFF);

    const int tid = threadIdx.x, lane = tid & 31, wid = tid >> 5;
    const int wr = wid & 3, wc = wid >> 2;
    const int gr = lane >> 2, tg = lane & 3;
    const int ldrow = tid >> 4, ldq = tid & 15;

    // one-time: weights -> smem tf32 swizzled, bias
    for (int idx = tid; idx < 128 * 128; idx += 512) {
        int n = idx >> 7, k = idx & 127;
        uint32_t off = (uint32_t)n * 512u + ((((uint32_t)k >> 2) ^ (n & 7)) << 4)
                     + ((uint32_t)k & 3) * 4u;
        *(uint32_t*)(smem + W1_OFF + off) = f2tf32(W1g[(size_t)k * H + n]);
        *(uint32_t*)(smem + W2_OFF + off) = f2tf32(W2g[(size_t)k * H + n]);
    }
    if (tid < 128) b2s[tid] = b2g[tid];

    // ldsm lane constants
    const int subA = lane & 7;
    const int arow0 = wr * 32 + ((lane >> 3) & 1) * 8 + subA;  // + mt*16
    const int hA = lane >> 4;
    const int subB = lane & 7;
    const int brow0 = wc * 32 + ((lane >> 4) & 1) * 8 + subB;  // + p*16
    const int hB = (lane >> 3) & 1;

    // per-thread chunk-load constants
    const uint32_t dsto = (uint32_t)ldrow * 256u
                        + (((uint32_t)ldq ^ ((uint32_t)ldrow & 7)) << 4);

    // buffer rotation state (SMEM byte offsets)
    uint32_t bA = BUF0, bB = BUF1, bC = BUF2;

    // prologue: issue c0, c1 of first tile
    {
        const int base = blockIdx.x * 128;
        if (blockIdx.x < numTiles) {
            #pragma unroll
            for (int it = 0; it < 4; ++it) {
                int row = ldrow + it * 32;
                CP_ASYNC16(sb + bA + dsto + it * 8192u,
                           &node[(size_t)(base + row) * H + ldq * 4]);
            }
        }
        CP_COMMIT();
        if (blockIdx.x < numTiles) {
            #pragma unroll
            for (int it = 0; it < 4; ++it) {
                int row = ldrow + it * 32;
                CP_ASYNC16(sb + bB + dsto + it * 8192u,
                           &node[(size_t)(base + row) * H + 64 + ldq * 4]);
            }
        }
        CP_COMMIT();
    }

    float acc[2][4][4];
    float2 cpre[2][2][4];

    for (int tile = blockIdx.x; tile < numTiles; tile += gridDim.x) {
        const int base = tile * 128;
        if (tid < 128) segs[tid] = seg[base + tid];
        CP_WAIT(1);
        __syncthreads();   // (a) c0 ready, segs/weights visible

        // prefetch c[seg] into regs (used in epilogue1)
        #pragma unroll
        for (int mt = 0; mt < 2; ++mt) {
            const int ra = wr * 32 + mt * 16 + gr;
            const int ga = segs[ra], gb = segs[ra + 8];
            #pragma unroll
            for (int nt = 0; nt < 4; ++nt) {
                const int col = wc * 32 + nt * 8 + 2 * tg;
                cpre[mt][0][nt] = *(const float2*)&g_c[(size_t)ga * H + col];
                cpre[mt][1][nt] = *(const float2*)&g_c[(size_t)gb * H + col];
            }
        }

        #pragma unroll
        for (int mt = 0; mt < 2; ++mt)
            #pragma unroll
            for (int nt = 0; nt < 4; ++nt)
                #pragma unroll
                for (int j = 0; j < 4; ++j) acc[mt][nt][j] = 0.0f;

        // ---- layer1 chunk0 (bA), then chunk1 (bB) ----
        #pragma unroll
        for (int c = 0; c < 2; ++c) {
            const uint32_t xb = sb + (c ? bB : bA);
            const int kqb = c * 16;
            #pragma unroll
            for (int ks = 0; ks < 8; ++ks) {
                uint32_t A[2][4], B[2][4];
                #pragma unroll
                for (int mt = 0; mt < 2; ++mt) {
                    uint32_t ad = xb + (uint32_t)(arow0 + mt * 16) * 256u
                                + ((((ks << 1) + hA) ^ subA) << 4);
                    ldsm4(A[mt][0], A[mt][1], A[mt][2], A[mt][3], ad);
                }
                #pragma unroll
                for (int p = 0; p < 2; ++p) {
                    uint32_t bd = sb + W1_OFF + (uint32_t)(brow0 + p * 16) * 512u
                                + (((kqb + (ks << 1) + hB) ^ subB) << 4);
                    ldsm4(B[p][0], B[p][1], B[p][2], B[p][3], bd);
                }
                #pragma unroll
                for (int mt = 0; mt < 2; ++mt) {
                    mma8(acc[mt][0], A[mt], B[0][0], B[0][1]);
                    mma8(acc[mt][1], A[mt], B[0][2], B[0][3]);
                    mma8(acc[mt][2], A[mt], B[1][0], B[1][1]);
                    mma8(acc[mt][3], A[mt], B[1][2], B[1][3]);
                }
            }
            if (c == 0) {
                CP_WAIT(0);
                __syncthreads();   // (b) c1 ready, c0 reads done
            }
        }
        __syncthreads();   // (c) all layer1 reads done before h overwrite

        // ---- epilogue1: + c[seg], relu, tf32 -> h halves (bA: k<64, bB: k>=64)
        {
            const int colb = wc * 32 + 2 * tg;
            const uint32_t hbuf = (wc < 2) ? bA : bB;
            #pragma unroll
            for (int mt = 0; mt < 2; ++mt) {
                const int ra = wr * 32 + mt * 16 + gr;
                #pragma unroll
                for (int nt = 0; nt < 4; ++nt) {
                    const int col = colb + nt * 8;
                    const int kk = col & 63;
                    uint32_t bo = ((((uint32_t)kk >> 2) ^ ((uint32_t)ra & 7)) << 4)
                                + ((uint32_t)kk & 3) * 4u;
                    uint2 v;
                    v.x = f2tf32(fmaxf(acc[mt][nt][0] + cpre[mt][0][nt].x, 0.0f));
                    v.y = f2tf32(fmaxf(acc[mt][nt][1] + cpre[mt][0][nt].y, 0.0f));
                    *(uint2*)(smem + hbuf + (uint32_t)ra * 256u + bo) = v;
                    uint32_t bo2 = ((((uint32_t)kk >> 2) ^ (((uint32_t)ra + 8) & 7)) << 4)
                                 + ((uint32_t)kk & 3) * 4u;
                    v.x = f2tf32(fmaxf(acc[mt][nt][2] + cpre[mt][1][nt].x, 0.0f));
                    v.y = f2tf32(fmaxf(acc[mt][nt][3] + cpre[mt][1][nt].y, 0.0f));
                    *(uint2*)(smem + hbuf + ((uint32_t)ra + 8) * 256u + bo2) = v;
                    #pragma unroll
                    for (int j = 0; j < 4; ++j) acc[mt][nt][j] = 0.0f;
                }
            }
        }
        __syncthreads();   // (d) h visible

        // issue next tile chunk0 -> bC (free)
        const int nxt = tile + gridDim.x;
        if (nxt < numTiles) {
            const int nb = nxt * 128;
            #pragma unroll
            for (int it = 0; it < 4; ++it) {
                int row = ldrow + it * 32;
                CP_ASYNC16(sb + bC + dsto + it * 8192u,
                           &node[(size_t)(nb + row) * H + ldq * 4]);
            }
        }
        CP_COMMIT();

        // ---- layer2: h (bA then bB) @ W2 ----
        #pragma unroll
        for (int c = 0; c < 2; ++c) {
            const uint32_t xb = sb + (c ? bB : bA);
            const int kqb = c * 16;
            #pragma unroll
            for (int ks = 0; ks < 8; ++ks) {
                uint32_t A[2][4], B[2][4];
                #pragma unroll
                for (int mt = 0; mt < 2; ++mt) {
                    uint32_t ad = xb + (uint32_t)(arow0 + mt * 16) * 256u
                                + ((((ks << 1) + hA) ^ subA) << 4);
                    ldsm4(A[mt][0], A[mt][1], A[mt][2], A[mt][3], ad);
                }
                #pragma unroll
                for (int p = 0; p < 2; ++p) {
                    uint32_t bd = sb + W2_OFF + (uint32_t)(brow0 + p * 16) * 512u
                                + (((kqb + (ks << 1) + hB) ^ subB) << 4);
                    ldsm4(B[p][0], B[p][1], B[p][2], B[p][3], bd);
                }
                #pragma unroll
                for (int mt = 0; mt < 2; ++mt) {
                    mma8(acc[mt][0], A[mt], B[0][0], B[0][1]);
                    mma8(acc[mt][1], A[mt], B[0][2], B[0][3]);
                    mma8(acc[mt][2], A[mt], B[1][0], B[1][1]);
                    mma8(acc[mt][3], A[mt], B[1][2], B[1][3]);
                }
            }
        }
        __syncthreads();   // (e) layer2 reads done; bA,bB free

        // issue next tile chunk1 -> bA
        if (nxt < numTiles) {
            const int nb = nxt * 128;
            #pragma unroll
            for (int it = 0; it < 4; ++it) {
                int row = ldrow + it * 32;
                CP_ASYNC16(sb + bA + dsto + it * 8192u,
                           &node[(size_t)(nb + row) * H + 64 + ldq * 4]);
            }
        }
        CP_COMMIT();

        // ---- epilogue2: +b2, relu, STG ----
        {
            const int colb = wc * 32 + 2 * tg;
            #pragma unroll
            for (int mt = 0; mt < 2; ++mt) {
                const int ra = base + wr * 32 + mt * 16 + gr;
                #pragma unroll
                for (int nt = 0; nt < 4; ++nt) {
                    const int col = colb + nt * 8;
                    const float bx = b2s[col], by = b2s[col + 1];
                    float2 v;
                    v.x = fmaxf(acc[mt][nt][0] + bx, 0.0f);
                    v.y = fmaxf(acc[mt][nt][1] + by, 0.0f);
                    *(float2*)&n_out[(size_t)ra * H + col] = v;
                    v.x = fmaxf(acc[mt][nt][2] + bx, 0.0f);
                    v.y = fmaxf(acc[mt][nt][3] + by, 0.0f);
                    *(float2*)&n_out[(size_t)(ra + 8) * H + col] = v;
                }
            }
        }

        // rotate: newA=C (has c0next), newB=A (getting c1next), newC=B
        uint32_t t0 = bC;
        bC = bB;
        bB = bA;
        bA = t0;
    }
}

extern "C" void kernel_launch(void* const* d_in, const int* in_sizes, int n_in,
                              void* d_out, int out_size) {
    const float* uset  = (const float*)d_in[0];   // [G, H]
    const float* unode = (const float*)d_in[1];   // [N, H]
    const int*   seg   = (const int*)d_in[2];     // [N]
    const float* Ws1   = (const float*)d_in[3];
    const float* bs1   = (const float*)d_in[4];
    const float* Ws2   = (const float*)d_in[5];
    const float* bs2   = (const float*)d_in[6];
    const float* Wn1   = (const float*)d_in[7];
    const float* bn1   = (const float*)d_in[8];
    const float* Wn2   = (const float*)d_in[9];
    const float* bn2   = (const float*)d_in[10];

    const int G = in_sizes[0] / H;
    const int N = in_sizes[1] / H;

    float* s_out = (float*)d_out;                  // [G, H]
    float* n_out = (float*)d_out + (size_t)G * H;  // [N, H]

    zero_agg_kernel<<<(G * H + 255) / 256, 256>>>(G * H);
    seg_sum_kernel<<<N / 128, 128>>>(unode, seg);
    set_mlp_c_kernel<<<G / 8, 128>>>(uset, Ws1, bs1, Ws2, bs2, Wn1, bn1, s_out);

    static int smem_set = 0;
    if (!smem_set) {
        cudaFuncSetAttribute(fused_node_mlp,
                             cudaFuncAttributeMaxDynamicSharedMemorySize, F_SMEM);
        smem_set = 1;
    }
    const int numTiles = N / 128;
    const int grid = numTiles < 148 ? numTiles : 148;
    fused_node_mlp<<<grid, 512, F_SMEM>>>(unode, seg, Wn1, Wn2, bn2, n_out, numTiles);
}

// round 7
// speedup vs baseline: 6.2248x; 1.1772x over previous
#include <cuda_runtime.h>
#include <cuda_fp16.h>
#include <cstdint>

#define H 128

// Scratch: segment sums [G,H]; c[g] = s[g] @ W1[128:256] + b1  (fp32).
__device__ float g_agg[4096 * 128];
__device__ float g_c[4096 * 128];

// ============================================================================
// Base-target PTX helpers
// ============================================================================
__device__ __forceinline__ uint32_t f2tf32(float f) {
    uint32_t u;
    asm("cvt.rna.tf32.f32 %0, %1;" : "=r"(u) : "f"(f));
    return u;
}
__device__ __forceinline__ uint32_t pack_f16x2(float lo, float hi) {
    uint32_t u;
    asm("cvt.rn.f16x2.f32 %0, %1, %2;" : "=r"(u) : "f"(hi), "f"(lo));
    return u;
}
__device__ __forceinline__ uint32_t smem_u32_of(const void* p) {
    uint32_t a;
    asm("{ .reg .u64 t; cvta.to.shared.u64 t, %1; cvt.u32.u64 %0, t; }"
        : "=r"(a) : "l"(p));
    return a;
}
__device__ __forceinline__ void mma8(float* d, const uint32_t* a,
                                     uint32_t b0, uint32_t b1) {
    asm volatile(
        "mma.sync.aligned.m16n8k8.row.col.f32.tf32.tf32.f32 "
        "{%0,%1,%2,%3},{%4,%5,%6,%7},{%8,%9},{%0,%1,%2,%3};"
        : "+f"(d[0]), "+f"(d[1]), "+f"(d[2]), "+f"(d[3])
        : "r"(a[0]), "r"(a[1]), "r"(a[2]), "r"(a[3]), "r"(b0), "r"(b1));
}
__device__ __forceinline__ void mma16(float* d, const uint32_t* a,
                                      uint32_t b0, uint32_t b1) {
    asm volatile(
        "mma.sync.aligned.m16n8k16.row.col.f32.f16.f16.f32 "
        "{%0,%1,%2,%3},{%4,%5,%6,%7},{%8,%9},{%0,%1,%2,%3};"
        : "+f"(d[0]), "+f"(d[1]), "+f"(d[2]), "+f"(d[3])
        : "r"(a[0]), "r"(a[1]), "r"(a[2]), "r"(a[3]), "r"(b0), "r"(b1));
}
__device__ __forceinline__ void ldsm4(uint32_t& r0, uint32_t& r1,
                                      uint32_t& r2, uint32_t& r3, uint32_t addr) {
    asm volatile("ldmatrix.sync.aligned.m8n8.x4.shared.b16 {%0,%1,%2,%3}, [%4];"
                 : "=r"(r0), "=r"(r1), "=r"(r2), "=r"(r3) : "r"(addr));
}
#define CP_ASYNC16(dst, src) \
    asm volatile("cp.async.cg.shared.global [%0], [%1], 16;" :: "r"(dst), "l"(src))
#define CP_COMMIT() asm volatile("cp.async.commit_group;" ::: "memory")
#define CP_WAIT(n)  asm volatile("cp.async.wait_group %0;" :: "n"(n) : "memory")

// ============================================================================
// Small kernels
// ============================================================================
__global__ void zero_agg_kernel(int n) {
    int i = blockIdx.x * blockDim.x + threadIdx.x;
    if (i < n) g_agg[i] = 0.0f;
}

// seg_sum v2: 512 rows/block, 256 threads. Thread (rp, c4): rp = row partition
// (64 serial rows), c4 = float4 column. One row = 32 threads x 16B, coalesced.
__global__ void seg_sum_kernel(const float4* __restrict__ node4,
                               const int* __restrict__ seg) {
    __shared__ int sseg[512];
    const int base = blockIdx.x * 512;
    const int tid = threadIdx.x;
    for (int i = tid; i < 512; i += 256) sseg[i] = seg[base + i];
    __syncthreads();
    const int c4 = tid & 31, rp = tid >> 5;
    const int r0 = rp * 64;
    float4 acc = make_float4(0.f, 0.f, 0.f, 0.f);
    int cur = sseg[r0];
    #pragma unroll 4
    for (int i = 0; i < 64; ++i) {
        const int r = r0 + i;
        const int id = sseg[r];
        if (id != cur) {
            float* dst = &g_agg[cur * H + c4 * 4];
            atomicAdd(dst + 0, acc.x); atomicAdd(dst + 1, acc.y);
            atomicAdd(dst + 2, acc.z); atomicAdd(dst + 3, acc.w);
            acc = make_float4(0.f, 0.f, 0.f, 0.f);
            cur = id;
        }
        float4 v = node4[(size_t)(base + r) * 32 + c4];
        acc.x += v.x; acc.y += v.y; acc.z += v.z; acc.w += v.w;
    }
    float* dst = &g_agg[cur * H + c4 * 4];
    atomicAdd(dst + 0, acc.x); atomicAdd(dst + 1, acc.y);
    atomicAdd(dst + 2, acc.z); atomicAdd(dst + 3, acc.w);
}

// set MLP + per-graph constant c[g] = s[g] @ W1[128:256] + b1 (exact fp32)
__global__ void set_mlp_c_kernel(const float* __restrict__ uset,
                                 const float* __restrict__ Ws1,
                                 const float* __restrict__ bs1,
                                 const float* __restrict__ Ws2,
                                 const float* __restrict__ bs2,
                                 const float* __restrict__ W1g,
                                 const float* __restrict__ b1g,
                                 float* __restrict__ s_out) {
    __shared__ float x[8][256];
    __shared__ float h1[8][128];
    __shared__ float sres[8][128];
    const int j = threadIdx.x;
    const int rbase = blockIdx.x * 8;
    for (int idx = j; idx < 8 * 256; idx += 128) {
        int r = idx >> 8, k = idx & 255;
        x[r][k] = (k < 128) ? g_agg[(rbase + r) * H + k]
                            : uset[(size_t)(rbase + r) * H + (k - 128)];
    }
    __syncthreads();
    float acc[8];
    float b1 = bs1[j];
    #pragma unroll
    for (int r = 0; r < 8; ++r) acc[r] = b1;
    for (int k = 0; k < 256; ++k) {
        float w = Ws1[k * H + j];
        #pragma unroll
        for (int r = 0; r < 8; ++r) acc[r] += x[r][k] * w;
    }
    #pragma unroll
    for (int r = 0; r < 8; ++r) h1[r][j] = fmaxf(acc[r], 0.0f);
    __syncthreads();
    float b2 = bs2[j];
    #pragma unroll
    for (int r = 0; r < 8; ++r) acc[r] = b2;
    for (int k = 0; k < 128; ++k) {
        float w = Ws2[k * H + j];
        #pragma unroll
        for (int r = 0; r < 8; ++r) acc[r] += h1[r][k] * w;
    }
    #pragma unroll
    for (int r = 0; r < 8; ++r) {
        float v = fmaxf(acc[r], 0.0f);
        sres[r][j] = v;
        s_out[(size_t)(rbase + r) * H + j] = v;
    }
    __syncthreads();
    float bb = b1g[j];
    #pragma unroll
    for (int r = 0; r < 8; ++r) acc[r] = bb;
    for (int k = 0; k < 128; ++k) {
        float w = W1g[(size_t)(128 + k) * H + j];
        #pragma unroll
        for (int r = 0; r < 8; ++r) acc[r] += sres[r][k] * w;
    }
    #pragma unroll
    for (int r = 0; r < 8; ++r) g_c[(size_t)(rbase + r) * H + j] = acc[r];
}

// ============================================================================
// Fused node MLP: layer1 tf32 (X streamed via cp.async, 2 buffers),
// layer2 fp16 m16n8k16 (h1 fp16 in own smem buffer, W2 fp16 resident).
// Weights W1a tf32 [n][128k] 512B/row, swizzle unit^(n&7).
// X chunks [128r][64k] tf32 256B/row. h1/W2 fp16 [r|n][128k] 256B/row.
// ============================================================================
#define W1_OFF   0        // 65536
#define W2_OFF   65536    // 32768 (fp16)
#define BUF0     98304    // 32768
#define BUF1     131072   // 32768
#define H1_OFF   163840   // 32768 (fp16)
#define B2S_OFF  196608   // 512
#define SEG_OFF  197120   // 512
#define F_SMEM   197632

__global__ void __launch_bounds__(512, 1)
fused_node_mlp(const float* __restrict__ node,
               const int* __restrict__ seg,
               const float* __restrict__ W1g,
               const float* __restrict__ W2g,
               const float* __restrict__ b2g,
               float* __restrict__ n_out,
               int numTiles) {
    extern __shared__ __align__(16) char smem[];
    const uint32_t sb = smem_u32_of(smem);
    float* b2s = (float*)(smem + B2S_OFF);
    int* segs = (int*)(smem + SEG_OFF);

    const int tid = threadIdx.x, lane = tid & 31, wid = tid >> 5;
    const int wr = wid & 3, wc = wid >> 2;
    const int gr = lane >> 2, tg = lane & 3;
    const int ldrow = tid >> 4, ldq = tid & 15;

    // one-time: W1a tf32, W2 fp16, bias
    for (int idx = tid; idx < 128 * 128; idx += 512) {
        int n = idx >> 7, k = idx & 127;
        uint32_t o1 = (uint32_t)n * 512u + ((((uint32_t)k >> 2) ^ (n & 7)) << 4)
                    + ((uint32_t)k & 3) * 4u;
        *(uint32_t*)(smem + W1_OFF + o1) = f2tf32(W1g[(size_t)k * H + n]);
        uint32_t o2 = (uint32_t)n * 256u + ((((uint32_t)k >> 3) ^ (n & 7)) << 4)
                    + ((uint32_t)k & 7) * 2u;
        *(__half*)(smem + W2_OFF + o2) = __float2half_rn(W2g[(size_t)k * H + n]);
    }
    if (tid < 128) b2s[tid] = b2g[tid];

    // ldsm lane constants (shared by tf32 and fp16 paths)
    const int subA = lane & 7;
    const int arow0 = wr * 32 + ((lane >> 3) & 1) * 8 + subA;  // + mt*16
    const int hA = lane >> 4;
    const int subB = lane & 7;
    const int brow0 = wc * 32 + ((lane >> 4) & 1) * 8 + subB;  // + p*16
    const int hB = (lane >> 3) & 1;

    const uint32_t dsto = (uint32_t)ldrow * 256u
                        + (((uint32_t)ldq ^ ((uint32_t)ldrow & 7)) << 4);

    // prologue: issue both chunks of first tile
    {
        const int base = blockIdx.x * 128;
        if (blockIdx.x < numTiles) {
            #pragma unroll
            for (int it = 0; it < 4; ++it) {
                int row = ldrow + it * 32;
                CP_ASYNC16(sb + BUF0 + dsto + it * 8192u,
                           &node[(size_t)(base + row) * H + ldq * 4]);
            }
        }
        CP_COMMIT();
        if (blockIdx.x < numTiles) {
            #pragma unroll
            for (int it = 0; it < 4; ++it) {
                int row = ldrow + it * 32;
                CP_ASYNC16(sb + BUF1 + dsto + it * 8192u,
                           &node[(size_t)(base + row) * H + 64 + ldq * 4]);
            }
        }
        CP_COMMIT();
    }

    float acc[2][4][4];
    float2 cpre[2][2][4];

    for (int tile = blockIdx.x; tile < numTiles; tile += gridDim.x) {
        const int base = tile * 128;
        if (tid < 128) segs[tid] = seg[base + tid];
        CP_WAIT(1);
        __syncthreads();   // (a) chunk0 ready; also fences prev-tile h1 reads

        // prefetch c[seg] (epilogue1 operand)
        #pragma unroll
        for (int mt = 0; mt < 2; ++mt) {
            const int ra = wr * 32 + mt * 16 + gr;
            const int ga = segs[ra], gb = segs[ra + 8];
            #pragma unroll
            for (int nt = 0; nt < 4; ++nt) {
                const int col = wc * 32 + nt * 8 + 2 * tg;
                cpre[mt][0][nt] = *(const float2*)&g_c[(size_t)ga * H + col];
                cpre[mt][1][nt] = *(const float2*)&g_c[(size_t)gb * H + col];
            }
        }

        #pragma unroll
        for (int mt = 0; mt < 2; ++mt)
            #pragma unroll
            for (int nt = 0; nt < 4; ++nt)
                #pragma unroll
                for (int j = 0; j < 4; ++j) acc[mt][nt][j] = 0.0f;

        // ---- layer1 (tf32): chunk0 (BUF0) then chunk1 (BUF1) ----
        #pragma unroll
        for (int c = 0; c < 2; ++c) {
            const uint32_t xb = sb + (c ? BUF1 : BUF0);
            const int kqb = c * 16;
            #pragma unroll
            for (int ks = 0; ks < 8; ++ks) {
                uint32_t A[2][4], B[2][4];
                #pragma unroll
                for (int mt = 0; mt < 2; ++mt) {
                    uint32_t ad = xb + (uint32_t)(arow0 + mt * 16) * 256u
                                + ((((ks << 1) + hA) ^ subA) << 4);
                    ldsm4(A[mt][0], A[mt][1], A[mt][2], A[mt][3], ad);
                }
                #pragma unroll
                for (int p = 0; p < 2; ++p) {
                    uint32_t bd = sb + W1_OFF + (uint32_t)(brow0 + p * 16) * 512u
                                + (((kqb + (ks << 1) + hB) ^ subB) << 4);
                    ldsm4(B[p][0], B[p][1], B[p][2], B[p][3], bd);
                }
                #pragma unroll
                for (int mt = 0; mt < 2; ++mt) {
                    mma8(acc[mt][0], A[mt], B[0][0], B[0][1]);
                    mma8(acc[mt][1], A[mt], B[0][2], B[0][3]);
                    mma8(acc[mt][2], A[mt], B[1][0], B[1][1]);
                    mma8(acc[mt][3], A[mt], B[1][2], B[1][3]);
                }
            }
            if (c == 0) {
                CP_WAIT(0);
                __syncthreads();   // (b) chunk1 ready
            }
        }

        // ---- epilogue1: + c[seg], relu, fp16 -> h1 buffer ----
        {
            #pragma unroll
            for (int mt = 0; mt < 2; ++mt) {
                const int ra = wr * 32 + mt * 16 + gr;
                #pragma unroll
                for (int nt = 0; nt < 4; ++nt) {
                    const int col = wc * 32 + nt * 8 + 2 * tg;
                    const uint32_t unit = (uint32_t)(col >> 3);
                    uint32_t v01 = pack_f16x2(
                        fmaxf(acc[mt][nt][0] + cpre[mt][0][nt].x, 0.0f),
                        fmaxf(acc[mt][nt][1] + cpre[mt][0][nt].y, 0.0f));
                    uint32_t o1 = (uint32_t)ra * 256u + ((unit ^ ((uint32_t)ra & 7)) << 4)
                                + ((uint32_t)col & 7) * 2u;
                    *(uint32_t*)(smem + H1_OFF + o1) = v01;
                    uint32_t v23 = pack_f16x2(
                        fmaxf(acc[mt][nt][2] + cpre[mt][1][nt].x, 0.0f),
                        fmaxf(acc[mt][nt][3] + cpre[mt][1][nt].y, 0.0f));
                    uint32_t o2 = (uint32_t)(ra + 8) * 256u
                                + ((unit ^ (((uint32_t)ra + 8) & 7)) << 4)
                                + ((uint32_t)col & 7) * 2u;
                    *(uint32_t*)(smem + H1_OFF + o2) = v23;
                    #pragma unroll
                    for (int j = 0; j < 4; ++j) acc[mt][nt][j] = 0.0f;
                }
            }
        }
        __syncthreads();   // (d) h1 visible; BUF0/1 reads done

        // issue next tile chunks (hidden behind layer2)
        const int nxt = tile + gridDim.x;
        if (nxt < numTiles) {
            const int nb = nxt * 128;
            #pragma unroll
            for (int it = 0; it < 4; ++it) {
                int row = ldrow + it * 32;
                CP_ASYNC16(sb + BUF0 + dsto + it * 8192u,
                           &node[(size_t)(nb + row) * H + ldq * 4]);
            }
        }
        CP_COMMIT();
        if (nxt < numTiles) {
            const int nb = nxt * 128;
            #pragma unroll
            for (int it = 0; it < 4; ++it) {
                int row = ldrow + it * 32;
                CP_ASYNC16(sb + BUF1 + dsto + it * 8192u,
                           &node[(size_t)(nb + row) * H + 64 + ldq * 4]);
            }
        }
        CP_COMMIT();

        // ---- layer2 (fp16 m16n8k16): h1 @ W2 ----
        #pragma unroll
        for (int ks = 0; ks < 8; ++ks) {
            uint32_t A[2][4], B[2][4];
            #pragma unroll
            for (int mt = 0; mt < 2; ++mt) {
                uint32_t ad = sb + H1_OFF + (uint32_t)(arow0 + mt * 16) * 256u
                            + ((((ks << 1) + hA) ^ subA) << 4);
                ldsm4(A[mt][0], A[mt][1], A[mt][2], A[mt][3], ad);
            }
            #pragma unroll
            for (int p = 0; p < 2; ++p) {
                uint32_t bd = sb + W2_OFF + (uint32_t)(brow0 + p * 16) * 256u
                            + ((((ks << 1) + hB) ^ subB) << 4);
                ldsm4(B[p][0], B[p][1], B[p][2], B[p][3], bd);
            }
            #pragma unroll
            for (int mt = 0; mt < 2; ++mt) {
                mma16(acc[mt][0], A[mt], B[0][0], B[0][1]);
                mma16(acc[mt][1], A[mt], B[0][2], B[0][3]);
                mma16(acc[mt][2], A[mt], B[1][0], B[1][1]);
                mma16(acc[mt][3], A[mt], B[1][2], B[1][3]);
            }
        }

        // ---- epilogue2: +b2, relu, STG ----
        {
            #pragma unroll
            for (int mt = 0; mt < 2; ++mt) {
                const int ra = base + wr * 32 + mt * 16 + gr;
                #pragma unroll
                for (int nt = 0; nt < 4; ++nt) {
                    const int col = wc * 32 + nt * 8 + 2 * tg;
                    const float bx = b2s[col], by = b2s[col + 1];
                    float2 v;
                    v.x = fmaxf(acc[mt][nt][0] + bx, 0.0f);
                    v.y = fmaxf(acc[mt][nt][1] + by, 0.0f);
                    *(float2*)&n_out[(size_t)ra * H + col] = v;
                    v.x = fmaxf(acc[mt][nt][2] + bx, 0.0f);
                    v.y = fmaxf(acc[mt][nt][3] + by, 0.0f);
                    *(float2*)&n_out[(size_t)(ra + 8) * H + col] = v;
                }
            }
        }
    }
}

extern "C" void kernel_launch(void* const* d_in, const int* in_sizes, int n_in,
                              void* d_out, int out_size) {
    const float* uset  = (const float*)d_in[0];   // [G, H]
    const float* unode = (const float*)d_in[1];   // [N, H]
    const int*   seg   = (const int*)d_in[2];     // [N]
    const float* Ws1   = (const float*)d_in[3];
    const float* bs1   = (const float*)d_in[4];
    const float* Ws2   = (const float*)d_in[5];
    const float* bs2   = (const float*)d_in[6];
    const float* Wn1   = (const float*)d_in[7];
    const float* bn1   = (const float*)d_in[8];
    const float* Wn2   = (const float*)d_in[9];
    const float* bn2   = (const float*)d_in[10];

    const int G = in_sizes[0] / H;
    const int N = in_sizes[1] / H;

    float* s_out = (float*)d_out;                  // [G, H]
    float* n_out = (float*)d_out + (size_t)G * H;  // [N, H]

    zero_agg_kernel<<<(G * H + 255) / 256, 256>>>(G * H);
    seg_sum_kernel<<<N / 512, 256>>>((const float4*)unode, seg);
    set_mlp_c_kernel<<<G / 8, 128>>>(uset, Ws1, bs1, Ws2, bs2, Wn1, bn1, s_out);

    static int smem_set = 0;
    if (!smem_set) {
        cudaFuncSetAttribute(fused_node_mlp,
                             cudaFuncAttributeMaxDynamicSharedMemorySize, F_SMEM);
        smem_set = 1;
    }
    const int numTiles = N / 128;
    const int grid = numTiles < 148 ? numTiles : 148;
    fused_node_mlp<<<grid, 512, F_SMEM>>>(unode, seg, Wn1, Wn2, bn2, n_out, numTiles);
}